// round 1
// baseline (speedup 1.0000x reference)
#include <cuda_runtime.h>
#include <math.h>

// Problem dims (fixed by the reference)
#define BB   2
#define LL   1024
#define DM   1024
#define DI   2048     // d_inner
#define NS   16       // d_state
#define RK   64       // dt_rank
#define SSMW 96       // dt_rank + 2*d_state

// ---------------- scratch (static __device__ — no allocs allowed) ----------
__device__ float g_proj[BB * LL * 2 * DI];   // (b, L, 4096): [0:2048)=hidden, [2048:4096)=gate
__device__ float g_ssm [BB * LL * SSMW];     // (b, L, 96): [0:64)=dtr, [64:80)=B, [80:96)=C
__device__ float g_dt  [BB * LL * DI];       // (b, L, d) softplus'd dt
__device__ float g_yfwd[BB * DI * LL];       // (b, d, L) forward-scan partial y
__device__ float g_scan[BB * LL * DI];       // (b, L, d) scan output (pre out_proj)

// ---------------------------------------------------------------------------
// Classic 128x128x8 register-blocked SGEMM:  C[M,N] = A[M,K] * B[N,K]^T
// Requires M%128==0, N%128==0, K%8==0, lda/ldb/ldc multiples of 4.
// epi==1: C = softplus(C + bias[col])
// ---------------------------------------------------------------------------
__global__ void __launch_bounds__(256) sgemm128(
    int K,
    const float* __restrict__ A, int lda,
    const float* __restrict__ B, int ldb,
    float* __restrict__ C, int ldc,
    const float* __restrict__ bias, int epi)
{
    __shared__ __align__(16) float As[8][132];
    __shared__ __align__(16) float Bs[8][132];

    const int tid  = threadIdx.x;
    const int tx   = tid & 15;
    const int ty   = tid >> 4;
    const int lrow = tid >> 1;          // 0..127
    const int lc4  = (tid & 1) * 4;     // 0 or 4

    const float* Ag = A + (size_t)(blockIdx.y * 128 + lrow) * lda + lc4;
    const float* Bg = B + (size_t)(blockIdx.x * 128 + lrow) * ldb + lc4;

    float acc[8][8];
#pragma unroll
    for (int i = 0; i < 8; i++)
#pragma unroll
        for (int j = 0; j < 8; j++) acc[i][j] = 0.f;

    for (int k0 = 0; k0 < K; k0 += 8) {
        float4 av = *(const float4*)(Ag + k0);
        float4 bv = *(const float4*)(Bg + k0);
        As[lc4 + 0][lrow] = av.x; As[lc4 + 1][lrow] = av.y;
        As[lc4 + 2][lrow] = av.z; As[lc4 + 3][lrow] = av.w;
        Bs[lc4 + 0][lrow] = bv.x; Bs[lc4 + 1][lrow] = bv.y;
        Bs[lc4 + 2][lrow] = bv.z; Bs[lc4 + 3][lrow] = bv.w;
        __syncthreads();
#pragma unroll
        for (int kk = 0; kk < 8; kk++) {
            float4 a0 = *(const float4*)&As[kk][ty * 8];
            float4 a1 = *(const float4*)&As[kk][ty * 8 + 4];
            float4 b0 = *(const float4*)&Bs[kk][tx * 8];
            float4 b1 = *(const float4*)&Bs[kk][tx * 8 + 4];
            float ar[8] = {a0.x, a0.y, a0.z, a0.w, a1.x, a1.y, a1.z, a1.w};
            float br[8] = {b0.x, b0.y, b0.z, b0.w, b1.x, b1.y, b1.z, b1.w};
#pragma unroll
            for (int i = 0; i < 8; i++)
#pragma unroll
                for (int j = 0; j < 8; j++)
                    acc[i][j] = fmaf(ar[i], br[j], acc[i][j]);
        }
        __syncthreads();
    }

    const int row0 = blockIdx.y * 128 + ty * 8;
    const int col0 = blockIdx.x * 128 + tx * 8;
#pragma unroll
    for (int i = 0; i < 8; i++) {
        float* crow = C + (size_t)(row0 + i) * ldc + col0;
#pragma unroll
        for (int j = 0; j < 8; j++) {
            float v = acc[i][j];
            if (epi == 1) {
                v += bias[col0 + j];
                v = (v > 20.f) ? v : log1pf(__expf(v));   // softplus
            }
            crow[j] = v;
        }
    }
}

// ---------------------------------------------------------------------------
// Small-tile SGEMM for the N=96 projection: C = A * B^T, tiles 32x32x32.
// Requires M%32==0, N%32==0, K%32==0.
// ---------------------------------------------------------------------------
__global__ void __launch_bounds__(256) sgemm32(
    int K,
    const float* __restrict__ A, int lda,
    const float* __restrict__ B, int ldb,
    float* __restrict__ C, int ldc)
{
    __shared__ float As[32][33];
    __shared__ float Bs[32][33];

    const int tid  = threadIdx.x;
    const int tx   = tid & 15;
    const int ty   = tid >> 4;
    const int lrow = tid >> 3;          // 0..31
    const int lc4  = (tid & 7) * 4;     // 0..28

    const float* Ag = A + (size_t)(blockIdx.y * 32 + lrow) * lda + lc4;
    const float* Bg = B + (size_t)(blockIdx.x * 32 + lrow) * ldb + lc4;

    float acc00 = 0.f, acc01 = 0.f, acc10 = 0.f, acc11 = 0.f;

    for (int k0 = 0; k0 < K; k0 += 32) {
        float4 av = *(const float4*)(Ag + k0);
        float4 bv = *(const float4*)(Bg + k0);
        As[lc4 + 0][lrow] = av.x; As[lc4 + 1][lrow] = av.y;
        As[lc4 + 2][lrow] = av.z; As[lc4 + 3][lrow] = av.w;
        Bs[lc4 + 0][lrow] = bv.x; Bs[lc4 + 1][lrow] = bv.y;
        Bs[lc4 + 2][lrow] = bv.z; Bs[lc4 + 3][lrow] = bv.w;
        __syncthreads();
#pragma unroll
        for (int kk = 0; kk < 32; kk++) {
            float a0 = As[kk][ty * 2];
            float a1 = As[kk][ty * 2 + 1];
            float b0 = Bs[kk][tx * 2];
            float b1 = Bs[kk][tx * 2 + 1];
            acc00 = fmaf(a0, b0, acc00);
            acc01 = fmaf(a0, b1, acc01);
            acc10 = fmaf(a1, b0, acc10);
            acc11 = fmaf(a1, b1, acc11);
        }
        __syncthreads();
    }

    const int row0 = blockIdx.y * 32 + ty * 2;
    const int col0 = blockIdx.x * 32 + tx * 2;
    C[(size_t)(row0    ) * ldc + col0    ] = acc00;
    C[(size_t)(row0    ) * ldc + col0 + 1] = acc01;
    C[(size_t)(row0 + 1) * ldc + col0    ] = acc10;
    C[(size_t)(row0 + 1) * ldc + col0 + 1] = acc11;
}

// ---------------------------------------------------------------------------
// Fused bidirectional selective-scan.
// One lane per (b, d, n): 65536 lanes. 16-lane shfl reduction over n.
// fwd:  h_t = dA_t h_{t-1} + u_t ;  y_fwd[t] = sum_n h_t C[t,n]
// bwd:  tail_t = dA_{t+1} bwd_{t+1} ; bwd_t = tail_t + u_t
//       y[t] = 1.3*(y_fwd[t] + sum_n tail_t C[t,n])
//       scan_out[t] = (y[t] + h[t]*D[d]) * silu(gate[t])
// ---------------------------------------------------------------------------
__global__ void __launch_bounds__(256) scan_kernel(
    const float* __restrict__ A_log,
    const float* __restrict__ Dvec)
{
    const int tid  = blockIdx.x * blockDim.x + threadIdx.x;  // 0..65535
    const int n    = tid & 15;
    const int pair = tid >> 4;       // 0..4095
    const int d    = pair & (DI - 1);
    const int b    = pair >> 11;

    const float An = -__expf(A_log[d * NS + n]);

    const float* ssm_b  = g_ssm  + (size_t)b * LL * SSMW;
    const float* dt_b   = g_dt   + (size_t)b * LL * DI + d;
    const float* hid_b  = g_proj + (size_t)b * LL * (2 * DI) + d;
    const float* gate_b = hid_b + DI;
    float* yf = g_yfwd + (size_t)pair * LL;
    float* so = g_scan + (size_t)b * LL * DI + d;

    // ---- forward pass ----
    float state = 0.f;
    for (int t = 0; t < LL; t++) {
        float dtv = dt_b[(size_t)t * DI];
        float hv  = hid_b[(size_t)t * (2 * DI)];
        float Bv  = ssm_b[t * SSMW + RK + n];
        float Cv  = ssm_b[t * SSMW + RK + NS + n];
        float dA  = __expf(An * dtv);
        float u   = dtv * Bv * hv;
        state = fmaf(dA, state, u);
        float c = state * Cv;
        c += __shfl_xor_sync(0xffffffffu, c, 1);
        c += __shfl_xor_sync(0xffffffffu, c, 2);
        c += __shfl_xor_sync(0xffffffffu, c, 4);
        c += __shfl_xor_sync(0xffffffffu, c, 8);
        if (n == 0) yf[t] = c;
    }

    // ---- backward pass (fused epilogue) ----
    const float Dd = Dvec[d];
    float S = 0.f, dA_next = 0.f;
    for (int t = LL - 1; t >= 0; t--) {
        float dtv = dt_b[(size_t)t * DI];
        float hv  = hid_b[(size_t)t * (2 * DI)];
        float Bv  = ssm_b[t * SSMW + RK + n];
        float Cv  = ssm_b[t * SSMW + RK + NS + n];
        float dA  = __expf(An * dtv);
        float u   = dtv * Bv * hv;
        float tail = dA_next * S;
        S = tail + u;
        dA_next = dA;
        float c = tail * Cv;
        c += __shfl_xor_sync(0xffffffffu, c, 1);
        c += __shfl_xor_sync(0xffffffffu, c, 2);
        c += __shfl_xor_sync(0xffffffffu, c, 4);
        c += __shfl_xor_sync(0xffffffffu, c, 8);
        if (n == 0) {
            float y = 1.3f * (yf[t] + c);
            float g = gate_b[(size_t)t * (2 * DI)];
            float sil = g / (1.f + __expf(-g));
            so[(size_t)t * DI] = (y + hv * Dd) * sil;
        }
    }
}

// ---------------------------------------------------------------------------
extern "C" void kernel_launch(void* const* d_in, const int* in_sizes, int n_in,
                              void* d_out, int out_size)
{
    const float* input      = (const float*)d_in[0];  // (2,1024,1024)
    const float* in_proj_w  = (const float*)d_in[1];  // (4096,1024)
    const float* x_proj_w   = (const float*)d_in[2];  // (96,2048)
    const float* dt_proj_w  = (const float*)d_in[3];  // (2048,64)
    const float* dt_proj_b  = (const float*)d_in[4];  // (2048,)
    const float* A_log      = (const float*)d_in[5];  // (2048,16)
    const float* Dvec       = (const float*)d_in[6];  // (2048,)
    const float* out_proj_w = (const float*)d_in[7];  // (1024,2048)
    float* out = (float*)d_out;

    float *pproj, *pssm, *pdt, *pscan;
    cudaGetSymbolAddress((void**)&pproj, g_proj);
    cudaGetSymbolAddress((void**)&pssm,  g_ssm);
    cudaGetSymbolAddress((void**)&pdt,   g_dt);
    cudaGetSymbolAddress((void**)&pscan, g_scan);

    const int M = BB * LL;  // 2048

    // 1) proj = input @ in_proj_w^T : (2048 x 4096), K=1024
    sgemm128<<<dim3(2 * DI / 128, M / 128), 256>>>(
        DM, input, DM, in_proj_w, DM, pproj, 2 * DI, nullptr, 0);

    // 2) ssm = hidden @ x_proj_w^T : (2048 x 96), K=2048
    sgemm32<<<dim3(SSMW / 32, M / 32), 256>>>(
        DI, pproj, 2 * DI, x_proj_w, DI, pssm, SSMW);

    // 3) dt = softplus(dtr @ dt_proj_w^T + b) : (2048 x 2048), K=64
    sgemm128<<<dim3(DI / 128, M / 128), 256>>>(
        RK, pssm, SSMW, dt_proj_w, RK, pdt, DI, dt_proj_b, 1);

    // 4) fused bidirectional scan + gating
    scan_kernel<<<(BB * DI * NS) / 256, 256>>>(A_log, Dvec);

    // 5) out = scan_out @ out_proj_w^T : (2048 x 1024), K=2048
    sgemm128<<<dim3(DM / 128, M / 128), 256>>>(
        DI, pscan, DI, out_proj_w, DI, out, DM, nullptr, 0);
}

// round 3
// speedup vs baseline: 1.9087x; 1.9087x over previous
#include <cuda_runtime.h>
#include <cuda_bf16.h>
#include <math.h>
#include <stdint.h>

// Problem dims (fixed)
#define BB   2
#define LL   1024
#define DM   1024
#define DI   2048
#define NS   16
#define RK   64
#define SSMW 96

// ---------------- scratch (static __device__) ------------------------------
__device__ float g_proj[BB * LL * 2 * DI];
__device__ float g_ssm [BB * LL * SSMW];
__device__ float g_dt  [BB * LL * DI];
__device__ float g_yfwd[BB * DI * LL];
__device__ float g_scan[BB * LL * DI];

__device__ __nv_bfloat16 g_in_hi[BB * LL * DM], g_in_lo[BB * LL * DM];
__device__ __nv_bfloat16 g_w1_hi[2 * DI * DM], g_w1_lo[2 * DI * DM];
__device__ __nv_bfloat16 g_so_hi[BB * LL * DI], g_so_lo[BB * LL * DI];
__device__ __nv_bfloat16 g_w4_hi[DM * DI],     g_w4_lo[DM * DI];

// ---------------- PTX helpers (non-arch-specific ISA only) -----------------
__device__ __forceinline__ uint32_t smem_u32(const void* p) {
    uint32_t a;
    asm("{ .reg .u64 t; cvta.to.shared.u64 t, %1; cvt.u32.u64 %0, t; }"
        : "=r"(a) : "l"(p));
    return a;
}
__device__ __forceinline__ void cp_async16(uint32_t dst, const void* src) {
    asm volatile("cp.async.cg.shared.global [%0], [%1], 16;" :: "r"(dst), "l"(src));
}
#define CP_COMMIT() asm volatile("cp.async.commit_group;" ::: "memory")
#define CP_WAIT(n)  asm volatile("cp.async.wait_group %0;" :: "n"(n) : "memory")

__device__ __forceinline__ void ldm_x4(uint32_t* r, uint32_t addr) {
    asm volatile("ldmatrix.sync.aligned.m8n8.x4.shared.b16 {%0,%1,%2,%3}, [%4];"
                 : "=r"(r[0]), "=r"(r[1]), "=r"(r[2]), "=r"(r[3]) : "r"(addr));
}
__device__ __forceinline__ void mma_bf16(float* c, const uint32_t* a,
                                         uint32_t b0, uint32_t b1) {
    asm volatile(
        "mma.sync.aligned.m16n8k16.row.col.f32.bf16.bf16.f32 "
        "{%0,%1,%2,%3}, {%4,%5,%6,%7}, {%8,%9}, {%0,%1,%2,%3};"
        : "+f"(c[0]), "+f"(c[1]), "+f"(c[2]), "+f"(c[3])
        : "r"(a[0]), "r"(a[1]), "r"(a[2]), "r"(a[3]), "r"(b0), "r"(b1));
}

// ---------------------------------------------------------------------------
// Warp-MMA split-bf16 GEMM:  C[M,N] = A[M,K] * B[N,K]^T  (fp32 out)
// C = Ah*Bh + Ah*Bl + Al*Bh chained into one fp32 accumulator.
// CTA tile 128x128, BK=32, 8 warps (2x4) with 64x32 warp tiles,
// double-buffered cp.async, 80B-padded smem rows (conflict-free ldmatrix).
// ---------------------------------------------------------------------------
#define ROWB   80                       // 64B data + 16B pad per smem row
#define PLANE  (128 * ROWB)             // 10240 B per plane
#define STAGE  (4 * PLANE)              // Ah, Al, Bh, Bl
#define GSMEM  (2 * STAGE)              // 81920 B

__global__ void __launch_bounds__(256, 1) gemm_mma(
    const __nv_bfloat16* __restrict__ Ahi, const __nv_bfloat16* __restrict__ Alo,
    const __nv_bfloat16* __restrict__ Bhi, const __nv_bfloat16* __restrict__ Blo,
    float* __restrict__ C, int K, int ldc)
{
    extern __shared__ char dsm[];
    const uint32_t sbase = smem_u32(dsm);

    const int tid  = threadIdx.x;
    const int lane = tid & 31;
    const int wid  = tid >> 5;
    const int wm0  = (wid >> 2) * 64;   // warp row offset in CTA tile
    const int wn0  = (wid & 3) * 32;    // warp col offset
    const int row0 = blockIdx.y * 128;
    const int col0 = blockIdx.x * 128;

    const __nv_bfloat16* planes[4] = {Ahi, Alo, Bhi, Blo};

    // ---- stage loader: 2048 16B-chunks, 8 per thread ----
    auto load_stage = [&](int ktile, int s) {
        const int k0 = ktile << 5;
        const uint32_t sb = sbase + s * STAGE;
#pragma unroll
        for (int it = 0; it < 8; it++) {
            int u = tid + it * 256;
            int p = u >> 9;             // plane 0..3
            int rem = u & 511;
            int r = rem >> 2;           // row 0..127
            int c = rem & 3;            // 16B chunk 0..3
            int grow = (p < 2 ? row0 : col0) + r;
            const __nv_bfloat16* src = planes[p] + (size_t)grow * K + k0 + c * 8;
            cp_async16(sb + p * PLANE + r * ROWB + c * 16, src);
        }
        CP_COMMIT();
    };

    float acc[4][4][4];
#pragma unroll
    for (int i = 0; i < 4; i++)
#pragma unroll
        for (int j = 0; j < 4; j++)
#pragma unroll
            for (int v = 0; v < 4; v++) acc[i][j][v] = 0.f;

    const int T = K >> 5;
    load_stage(0, 0);
    load_stage(1, 1);

    const int lrow = lane & 15;         // ldmatrix row within 16
    const int lcol = lane >> 4;         // ldmatrix 16B column select

    for (int t = 0; t < T; t++) {
        const int s = t & 1;
        if (t < T - 1) { CP_WAIT(1); } else { CP_WAIT(0); }
        __syncthreads();

        const uint32_t sb = sbase + s * STAGE;
#pragma unroll
        for (int kh = 0; kh < 2; kh++) {
            const uint32_t kb = (kh * 2 + lcol) * 16;
            uint32_t ah[4][4], al[4][4], bh[2][4], bl[2][4];
#pragma unroll
            for (int mt = 0; mt < 4; mt++) {
                uint32_t ro = (uint32_t)(wm0 + mt * 16 + lrow) * ROWB + kb;
                ldm_x4(ah[mt], sb + ro);
                ldm_x4(al[mt], sb + PLANE + ro);
            }
#pragma unroll
            for (int p = 0; p < 2; p++) {
                uint32_t ro = (uint32_t)(wn0 + p * 16 + lrow) * ROWB + kb;
                ldm_x4(bh[p], sb + 2 * PLANE + ro);
                ldm_x4(bl[p], sb + 3 * PLANE + ro);
            }
#pragma unroll
            for (int mt = 0; mt < 4; mt++)
#pragma unroll
                for (int nt = 0; nt < 4; nt++) {
                    int pi = nt >> 1, hf = nt & 1;
                    mma_bf16(acc[mt][nt], ah[mt], bh[pi][hf], bh[pi][hf + 2]);
                    mma_bf16(acc[mt][nt], ah[mt], bl[pi][hf], bl[pi][hf + 2]);
                    mma_bf16(acc[mt][nt], al[mt], bh[pi][hf], bh[pi][hf + 2]);
                }
        }
        __syncthreads();
        if (t + 2 < T) load_stage(t + 2, s);
    }

    // ---- epilogue: fragment -> global ----
    const int crow = row0 + wm0 + (lane >> 2);
    const int ccol = col0 + wn0 + (lane & 3) * 2;
#pragma unroll
    for (int mt = 0; mt < 4; mt++)
#pragma unroll
        for (int nt = 0; nt < 4; nt++) {
#pragma unroll
            for (int hf = 0; hf < 2; hf++) {
                float2* dst = (float2*)(C + (size_t)(crow + mt * 16 + hf * 8) * ldc
                                          + ccol + nt * 8);
                *dst = make_float2(acc[mt][nt][hf * 2], acc[mt][nt][hf * 2 + 1]);
            }
        }
}

// ---------------------------------------------------------------------------
// fp32 -> (hi, lo) bf16 split conversion
// ---------------------------------------------------------------------------
__global__ void __launch_bounds__(256) cvt_split(
    const float* __restrict__ x, __nv_bfloat16* __restrict__ hi,
    __nv_bfloat16* __restrict__ lo, int n4)
{
    int i = blockIdx.x * blockDim.x + threadIdx.x;
    if (i >= n4) return;
    float4 v = ((const float4*)x)[i];
    __nv_bfloat16 h0 = __float2bfloat16(v.x);
    __nv_bfloat16 h1 = __float2bfloat16(v.y);
    __nv_bfloat16 h2 = __float2bfloat16(v.z);
    __nv_bfloat16 h3 = __float2bfloat16(v.w);
    __nv_bfloat16 l0 = __float2bfloat16(v.x - __bfloat162float(h0));
    __nv_bfloat16 l1 = __float2bfloat16(v.y - __bfloat162float(h1));
    __nv_bfloat16 l2 = __float2bfloat16(v.z - __bfloat162float(h2));
    __nv_bfloat16 l3 = __float2bfloat16(v.w - __bfloat162float(h3));
    ((__nv_bfloat162*)hi)[i * 2 + 0] = __nv_bfloat162(h0, h1);
    ((__nv_bfloat162*)hi)[i * 2 + 1] = __nv_bfloat162(h2, h3);
    ((__nv_bfloat162*)lo)[i * 2 + 0] = __nv_bfloat162(l0, l1);
    ((__nv_bfloat162*)lo)[i * 2 + 1] = __nv_bfloat162(l2, l3);
}

// ---------------------------------------------------------------------------
// SIMT GEMMs for the small projections
// ---------------------------------------------------------------------------
__global__ void __launch_bounds__(256) sgemm128(
    int K,
    const float* __restrict__ A, int lda,
    const float* __restrict__ B, int ldb,
    float* __restrict__ C, int ldc,
    const float* __restrict__ bias, int epi)
{
    __shared__ __align__(16) float As[8][132];
    __shared__ __align__(16) float Bs[8][132];
    const int tid  = threadIdx.x;
    const int tx   = tid & 15;
    const int ty   = tid >> 4;
    const int lrow = tid >> 1;
    const int lc4  = (tid & 1) * 4;
    const float* Ag = A + (size_t)(blockIdx.y * 128 + lrow) * lda + lc4;
    const float* Bg = B + (size_t)(blockIdx.x * 128 + lrow) * ldb + lc4;
    float acc[8][8];
#pragma unroll
    for (int i = 0; i < 8; i++)
#pragma unroll
        for (int j = 0; j < 8; j++) acc[i][j] = 0.f;
    for (int k0 = 0; k0 < K; k0 += 8) {
        float4 av = *(const float4*)(Ag + k0);
        float4 bv = *(const float4*)(Bg + k0);
        As[lc4 + 0][lrow] = av.x; As[lc4 + 1][lrow] = av.y;
        As[lc4 + 2][lrow] = av.z; As[lc4 + 3][lrow] = av.w;
        Bs[lc4 + 0][lrow] = bv.x; Bs[lc4 + 1][lrow] = bv.y;
        Bs[lc4 + 2][lrow] = bv.z; Bs[lc4 + 3][lrow] = bv.w;
        __syncthreads();
#pragma unroll
        for (int kk = 0; kk < 8; kk++) {
            float4 a0 = *(const float4*)&As[kk][ty * 8];
            float4 a1 = *(const float4*)&As[kk][ty * 8 + 4];
            float4 b0 = *(const float4*)&Bs[kk][tx * 8];
            float4 b1 = *(const float4*)&Bs[kk][tx * 8 + 4];
            float ar[8] = {a0.x, a0.y, a0.z, a0.w, a1.x, a1.y, a1.z, a1.w};
            float br[8] = {b0.x, b0.y, b0.z, b0.w, b1.x, b1.y, b1.z, b1.w};
#pragma unroll
            for (int i = 0; i < 8; i++)
#pragma unroll
                for (int j = 0; j < 8; j++)
                    acc[i][j] = fmaf(ar[i], br[j], acc[i][j]);
        }
        __syncthreads();
    }
    const int row0 = blockIdx.y * 128 + ty * 8;
    const int col0 = blockIdx.x * 128 + tx * 8;
#pragma unroll
    for (int i = 0; i < 8; i++) {
        float* crow = C + (size_t)(row0 + i) * ldc + col0;
#pragma unroll
        for (int j = 0; j < 8; j++) {
            float v = acc[i][j];
            if (epi == 1) {
                v += bias[col0 + j];
                v = (v > 20.f) ? v : log1pf(__expf(v));
            }
            crow[j] = v;
        }
    }
}

__global__ void __launch_bounds__(256) sgemm32(
    int K,
    const float* __restrict__ A, int lda,
    const float* __restrict__ B, int ldb,
    float* __restrict__ C, int ldc)
{
    __shared__ float As[32][33];
    __shared__ float Bs[32][33];
    const int tid  = threadIdx.x;
    const int tx   = tid & 15;
    const int ty   = tid >> 4;
    const int lrow = tid >> 3;
    const int lc4  = (tid & 7) * 4;
    const float* Ag = A + (size_t)(blockIdx.y * 32 + lrow) * lda + lc4;
    const float* Bg = B + (size_t)(blockIdx.x * 32 + lrow) * ldb + lc4;
    float acc00 = 0.f, acc01 = 0.f, acc10 = 0.f, acc11 = 0.f;
    for (int k0 = 0; k0 < K; k0 += 32) {
        float4 av = *(const float4*)(Ag + k0);
        float4 bv = *(const float4*)(Bg + k0);
        As[lc4 + 0][lrow] = av.x; As[lc4 + 1][lrow] = av.y;
        As[lc4 + 2][lrow] = av.z; As[lc4 + 3][lrow] = av.w;
        Bs[lc4 + 0][lrow] = bv.x; Bs[lc4 + 1][lrow] = bv.y;
        Bs[lc4 + 2][lrow] = bv.z; Bs[lc4 + 3][lrow] = bv.w;
        __syncthreads();
#pragma unroll
        for (int kk = 0; kk < 32; kk++) {
            float a0 = As[kk][ty * 2];
            float a1 = As[kk][ty * 2 + 1];
            float b0 = Bs[kk][tx * 2];
            float b1 = Bs[kk][tx * 2 + 1];
            acc00 = fmaf(a0, b0, acc00);
            acc01 = fmaf(a0, b1, acc01);
            acc10 = fmaf(a1, b0, acc10);
            acc11 = fmaf(a1, b1, acc11);
        }
        __syncthreads();
    }
    const int row0 = blockIdx.y * 32 + ty * 2;
    const int col0 = blockIdx.x * 32 + tx * 2;
    C[(size_t)(row0    ) * ldc + col0    ] = acc00;
    C[(size_t)(row0    ) * ldc + col0 + 1] = acc01;
    C[(size_t)(row0 + 1) * ldc + col0    ] = acc10;
    C[(size_t)(row0 + 1) * ldc + col0 + 1] = acc11;
}

// ---------------------------------------------------------------------------
// Fused bidirectional selective scan
// ---------------------------------------------------------------------------
__global__ void __launch_bounds__(256) scan_kernel(
    const float* __restrict__ A_log,
    const float* __restrict__ Dvec)
{
    const int tid  = blockIdx.x * blockDim.x + threadIdx.x;
    const int n    = tid & 15;
    const int pair = tid >> 4;
    const int d    = pair & (DI - 1);
    const int b    = pair >> 11;

    const float An = -__expf(A_log[d * NS + n]);
    const float* ssm_b  = g_ssm  + (size_t)b * LL * SSMW;
    const float* dt_b   = g_dt   + (size_t)b * LL * DI + d;
    const float* hid_b  = g_proj + (size_t)b * LL * (2 * DI) + d;
    const float* gate_b = hid_b + DI;
    float* yf = g_yfwd + (size_t)pair * LL;
    float* so = g_scan + (size_t)b * LL * DI + d;

    float state = 0.f;
    for (int t = 0; t < LL; t++) {
        float dtv = dt_b[(size_t)t * DI];
        float hv  = hid_b[(size_t)t * (2 * DI)];
        float Bv  = ssm_b[t * SSMW + RK + n];
        float Cv  = ssm_b[t * SSMW + RK + NS + n];
        float dA  = __expf(An * dtv);
        float u   = dtv * Bv * hv;
        state = fmaf(dA, state, u);
        float c = state * Cv;
        c += __shfl_xor_sync(0xffffffffu, c, 1);
        c += __shfl_xor_sync(0xffffffffu, c, 2);
        c += __shfl_xor_sync(0xffffffffu, c, 4);
        c += __shfl_xor_sync(0xffffffffu, c, 8);
        if (n == 0) yf[t] = c;
    }

    const float Dd = Dvec[d];
    float S = 0.f, dA_next = 0.f;
    for (int t = LL - 1; t >= 0; t--) {
        float dtv = dt_b[(size_t)t * DI];
        float hv  = hid_b[(size_t)t * (2 * DI)];
        float Bv  = ssm_b[t * SSMW + RK + n];
        float Cv  = ssm_b[t * SSMW + RK + NS + n];
        float dA  = __expf(An * dtv);
        float u   = dtv * Bv * hv;
        float tail = dA_next * S;
        S = tail + u;
        dA_next = dA;
        float c = tail * Cv;
        c += __shfl_xor_sync(0xffffffffu, c, 1);
        c += __shfl_xor_sync(0xffffffffu, c, 2);
        c += __shfl_xor_sync(0xffffffffu, c, 4);
        c += __shfl_xor_sync(0xffffffffu, c, 8);
        if (n == 0) {
            float y = 1.3f * (yf[t] + c);
            float g = gate_b[(size_t)t * (2 * DI)];
            float sil = g / (1.f + __expf(-g));
            so[(size_t)t * DI] = (y + hv * Dd) * sil;
        }
    }
}

// ---------------------------------------------------------------------------
extern "C" void kernel_launch(void* const* d_in, const int* in_sizes, int n_in,
                              void* d_out, int out_size)
{
    const float* input      = (const float*)d_in[0];
    const float* in_proj_w  = (const float*)d_in[1];
    const float* x_proj_w   = (const float*)d_in[2];
    const float* dt_proj_w  = (const float*)d_in[3];
    const float* dt_proj_b  = (const float*)d_in[4];
    const float* A_log      = (const float*)d_in[5];
    const float* Dvec       = (const float*)d_in[6];
    const float* out_proj_w = (const float*)d_in[7];
    float* out = (float*)d_out;

    float *pproj, *pssm, *pdt, *pscan;
    __nv_bfloat16 *pin_h, *pin_l, *pw1_h, *pw1_l, *pso_h, *pso_l, *pw4_h, *pw4_l;
    cudaGetSymbolAddress((void**)&pproj, g_proj);
    cudaGetSymbolAddress((void**)&pssm,  g_ssm);
    cudaGetSymbolAddress((void**)&pdt,   g_dt);
    cudaGetSymbolAddress((void**)&pscan, g_scan);
    cudaGetSymbolAddress((void**)&pin_h, g_in_hi);
    cudaGetSymbolAddress((void**)&pin_l, g_in_lo);
    cudaGetSymbolAddress((void**)&pw1_h, g_w1_hi);
    cudaGetSymbolAddress((void**)&pw1_l, g_w1_lo);
    cudaGetSymbolAddress((void**)&pso_h, g_so_hi);
    cudaGetSymbolAddress((void**)&pso_l, g_so_lo);
    cudaGetSymbolAddress((void**)&pw4_h, g_w4_hi);
    cudaGetSymbolAddress((void**)&pw4_l, g_w4_lo);

    cudaFuncSetAttribute(gemm_mma, cudaFuncAttributeMaxDynamicSharedMemorySize, GSMEM);

    const int M = BB * LL;  // 2048

    // converts for GEMM1
    cvt_split<<<(M * DM / 4 + 255) / 256, 256>>>(input, pin_h, pin_l, M * DM / 4);
    cvt_split<<<(2 * DI * DM / 4 + 255) / 256, 256>>>(in_proj_w, pw1_h, pw1_l,
                                                      2 * DI * DM / 4);

    // 1) proj = input @ in_proj_w^T : (2048 x 4096), K=1024  [HMMA]
    gemm_mma<<<dim3(2 * DI / 128, M / 128), 256, GSMEM>>>(
        pin_h, pin_l, pw1_h, pw1_l, pproj, DM, 2 * DI);

    // 2) ssm = hidden @ x_proj_w^T : (2048 x 96), K=2048  [SIMT]
    sgemm32<<<dim3(SSMW / 32, M / 32), 256>>>(DI, pproj, 2 * DI, x_proj_w, DI, pssm, SSMW);

    // 3) dt = softplus(dtr @ dt_proj_w^T + b) : (2048 x 2048), K=64  [SIMT]
    sgemm128<<<dim3(DI / 128, M / 128), 256>>>(RK, pssm, SSMW, dt_proj_w, RK, pdt, DI,
                                               dt_proj_b, 1);

    // 4) fused bidirectional scan
    scan_kernel<<<(BB * DI * NS) / 256, 256>>>(A_log, Dvec);

    // converts for GEMM4
    cvt_split<<<(M * DI / 4 + 255) / 256, 256>>>(pscan, pso_h, pso_l, M * DI / 4);
    cvt_split<<<(DM * DI / 4 + 255) / 256, 256>>>(out_proj_w, pw4_h, pw4_l, DM * DI / 4);

    // 5) out = scan_out @ out_proj_w^T : (2048 x 1024), K=2048  [HMMA]
    gemm_mma<<<dim3(DM / 128, M / 128), 256, GSMEM>>>(
        pso_h, pso_l, pw4_h, pw4_l, out, DI, DM);
}